// round 2
// baseline (speedup 1.0000x reference)
#include <cuda_runtime.h>
#include <cuda_bf16.h>
#include <math.h>

// ============================================================================
// AdaptiveLoss: adaptive softmax loss, computed without materializing the
// [B, VOCAB] logprob matrix.
//
// Pipeline:
//  1. detect dtype of targets (int64 vs int32) and mask (u8 vs i32)
//  2. proj GEMMs: h_i = features @ proj_i.T       (4 small GEMMs)
//  3. GEMM+online-LSE: per-row (max, sumexp) partials per 128-col chunk for
//     head logits and each cluster's logits; head pass also captures the
//     4 tail logits (cols 10000..10003).
//  4. combine partials -> per-row LSE per matrix
//  5. loss kernel: warp per target, recompute the single needed logit by a
//     short dot product, assemble logprob, accumulate weighted loss per row
//  6. final reduction -> scalar
// ============================================================================

#define B_ROWS 1024
#define D_DIM  1024
#define NHEAD  10004

// chunk = 128 columns
__device__ const int d_chunks[5] = {79, 79, 157, 313, 157};         // head,c0,c1,c2,c3
__device__ const int d_pbase[5]  = {0, 80896, 161792, 322560, 643072}; // cumulative *1024
#define PM_TOTAL 803840

// scratch (static device allocations are allowed)
__device__ float g_h0[B_ROWS * 512];
__device__ float g_h1[B_ROWS * 256];
__device__ float g_h2[B_ROWS * 128];
__device__ float g_h3[B_ROWS * 64];
__device__ float g_pm[PM_TOTAL];
__device__ float g_ps[PM_TOTAL];
__device__ float g_lse[5 * B_ROWS];
__device__ float g_tail[B_ROWS * 4];
__device__ float g_num[B_ROWS];
__device__ float g_den[B_ROWS];
__device__ int   g_flags[2];   // [0]: targets are int64, [1]: mask is int32

// ----------------------------------------------------------------------------
__global__ void detect_kernel(const void* tgt, const void* msk) {
    const int* ti = (const int*)tgt;
    int nz = 0;
    for (int j = 0; j < 128; j++) nz += (ti[2 * j + 1] != 0);
    g_flags[0] = (nz <= 8) ? 1 : 0;   // int64: high 32-bit words all zero

    const unsigned int* mw = (const unsigned int*)msk;
    int looks_i32 = 1;
    for (int j = 0; j < 64; j++) if (mw[j] > 255u) looks_i32 = 0;
    g_flags[1] = looks_i32;
}

__global__ void zero_kernel() {
    int i = blockIdx.x * blockDim.x + threadIdx.x;
    if (i < B_ROWS) { g_num[i] = 0.f; g_den[i] = 0.f; }
}

// ----------------------------------------------------------------------------
// Tiled GEMM: C[M,N] = A[M,K] @ W[N,K]^T.  128x128 tile, 8x8 per thread.
// MODE 0: store C into g_h{outSel}.
// MODE 1: per-row online (max, sumexp) over this 128-col chunk -> g_pm/g_ps;
//         matIdx = outSel (0=head: also capture tail logits 10000..10003).
// aSel: -1 -> use Aext, else g_h{aSel}.
// ----------------------------------------------------------------------------
template <int MODE>
__global__ __launch_bounds__(256, 2)
void gemm_tile_kernel(const float* __restrict__ Aext,
                      const float* __restrict__ W,
                      int N, int K, int aSel, int outSel)
{
    __shared__ float As[16][128];
    __shared__ float Bs[16][128];

    const float* A = Aext;
    if      (aSel == 0) A = g_h0;
    else if (aSel == 1) A = g_h1;
    else if (aSel == 2) A = g_h2;
    else if (aSel == 3) A = g_h3;

    const int t  = threadIdx.x;
    const int tx = t & 15;
    const int ty = t >> 4;
    const int rowBase = blockIdx.x * 128;
    const int colBase = blockIdx.y * 128;

    float acc[8][8];
#pragma unroll
    for (int i = 0; i < 8; i++)
#pragma unroll
        for (int j = 0; j < 8; j++) acc[i][j] = 0.f;

    for (int k0 = 0; k0 < K; k0 += 16) {
#pragma unroll
        for (int u = 0; u < 2; u++) {
            int f = t + u * 256;
            int r = f >> 2;        // 0..127
            int q = f & 3;         // k quad
            float4 a4 = *(const float4*)(A + (size_t)(rowBase + r) * K + k0 + q * 4);
            As[q * 4 + 0][r] = a4.x; As[q * 4 + 1][r] = a4.y;
            As[q * 4 + 2][r] = a4.z; As[q * 4 + 3][r] = a4.w;
            int n = colBase + r;
            float4 b4 = make_float4(0.f, 0.f, 0.f, 0.f);
            if (n < N) b4 = *(const float4*)(W + (size_t)n * K + k0 + q * 4);
            Bs[q * 4 + 0][r] = b4.x; Bs[q * 4 + 1][r] = b4.y;
            Bs[q * 4 + 2][r] = b4.z; Bs[q * 4 + 3][r] = b4.w;
        }
        __syncthreads();
#pragma unroll
        for (int k = 0; k < 16; k++) {
            float a[8], b[8];
            *(float4*)&a[0] = *(const float4*)&As[k][ty * 8];
            *(float4*)&a[4] = *(const float4*)&As[k][ty * 8 + 4];
            *(float4*)&b[0] = *(const float4*)&Bs[k][tx * 8];
            *(float4*)&b[4] = *(const float4*)&Bs[k][tx * 8 + 4];
#pragma unroll
            for (int i = 0; i < 8; i++)
#pragma unroll
                for (int j = 0; j < 8; j++)
                    acc[i][j] = fmaf(a[i], b[j], acc[i][j]);
        }
        __syncthreads();
    }

    if (MODE == 0) {
        float* C = (outSel == 0) ? g_h0 : (outSel == 1) ? g_h1
                 : (outSel == 2) ? g_h2 : g_h3;
#pragma unroll
        for (int i = 0; i < 8; i++) {
            int r = rowBase + ty * 8 + i;
#pragma unroll
            for (int j = 0; j < 8; j++) {
                int c = colBase + tx * 8 + j;
                if (c < N) C[(size_t)r * N + c] = acc[i][j];
            }
        }
    } else {
        const int matIdx = outSel;
        if (matIdx == 0) {
#pragma unroll
            for (int i = 0; i < 8; i++)
#pragma unroll
                for (int j = 0; j < 8; j++) {
                    int c = colBase + tx * 8 + j;
                    if (c >= 10000 && c < 10004)
                        g_tail[(rowBase + ty * 8 + i) * 4 + (c - 10000)] = acc[i][j];
                }
        }
        const int chunks = d_chunks[matIdx];
        float* pm = g_pm + d_pbase[matIdx];
        float* ps = g_ps + d_pbase[matIdx];
#pragma unroll
        for (int i = 0; i < 8; i++) {
            float m = -INFINITY;
#pragma unroll
            for (int j = 0; j < 8; j++) {
                int c = colBase + tx * 8 + j;
                if (c < N) m = fmaxf(m, acc[i][j]);
            }
            float s = 0.f;
            if (m > -INFINITY) {
#pragma unroll
                for (int j = 0; j < 8; j++) {
                    int c = colBase + tx * 8 + j;
                    if (c < N) s += expf(acc[i][j] - m);
                }
            }
#pragma unroll
            for (int o = 1; o < 16; o <<= 1) {
                float mo = __shfl_xor_sync(0xffffffffu, m, o);
                float so = __shfl_xor_sync(0xffffffffu, s, o);
                float M2 = fmaxf(m, mo);
                if (M2 == -INFINITY) { m = M2; s = 0.f; }
                else { s = s * expf(m - M2) + so * expf(mo - M2); m = M2; }
            }
            if (tx == 0) {
                int r = rowBase + ty * 8 + i;
                pm[(size_t)r * chunks + blockIdx.y] = m;
                ps[(size_t)r * chunks + blockIdx.y] = s;
            }
        }
    }
}

// ----------------------------------------------------------------------------
__global__ void combine_kernel() {
    int row = blockIdx.x, mat = blockIdx.y, lane = threadIdx.x;
    int chunks = d_chunks[mat];
    const float* pm = g_pm + d_pbase[mat] + (size_t)row * chunks;
    const float* ps = g_ps + d_pbase[mat] + (size_t)row * chunks;
    float m = -INFINITY, s = 0.f;
    for (int c = lane; c < chunks; c += 32) {
        float mo = pm[c], so = ps[c];
        float M2 = fmaxf(m, mo);
        if (M2 == -INFINITY) { m = M2; s = 0.f; }
        else { s = s * expf(m - M2) + so * expf(mo - M2); m = M2; }
    }
    for (int o = 1; o < 32; o <<= 1) {
        float mo = __shfl_xor_sync(0xffffffffu, m, o);
        float so = __shfl_xor_sync(0xffffffffu, s, o);
        float M2 = fmaxf(m, mo);
        if (M2 == -INFINITY) { m = M2; s = 0.f; }
        else { s = s * expf(m - M2) + so * expf(mo - M2); m = M2; }
    }
    if (lane == 0) g_lse[mat * B_ROWS + row] = m + logf(s);
}

// ----------------------------------------------------------------------------
// One warp per (b, t) target: recompute the needed logit by dot product.
// ----------------------------------------------------------------------------
__global__ void loss_kernel(const float* __restrict__ feat,
                            const float* __restrict__ headW,
                            const float* __restrict__ out0,
                            const float* __restrict__ out1,
                            const float* __restrict__ out2,
                            const float* __restrict__ out3,
                            const float* __restrict__ discard,
                            const void* __restrict__ tgt,
                            const void* __restrict__ msk)
{
    int gwarp = (blockIdx.x * blockDim.x + threadIdx.x) >> 5;
    int lane  = threadIdx.x & 31;
    if (gwarp >= B_ROWS * 128) return;
    int b = gwarp >> 7;

    long long v;
    if (g_flags[0]) v = ((const long long*)tgt)[gwarp];
    else            v = (long long)((const int*)tgt)[gwarp];

    float mk;
    if (g_flags[1]) mk = (((const int*)msk)[gwarp] != 0) ? 1.f : 0.f;
    else            mk = (((const unsigned char*)msk)[gwarp] != 0) ? 1.f : 0.f;

    const float *a, *w;
    int Kd; float lse, extra;
    float hlse = g_lse[b];
    if (v < 10000) {
        a = feat + (size_t)b * 1024; w = headW + (size_t)v * 1024;
        Kd = 1024; lse = hlse; extra = 0.f;
    } else if (v < 20000) {
        a = g_h0 + (size_t)b * 512; w = out0 + (size_t)(v - 10000) * 512;
        Kd = 512; lse = g_lse[1 * B_ROWS + b]; extra = g_tail[b * 4 + 0] - hlse;
    } else if (v < 40000) {
        a = g_h1 + (size_t)b * 256; w = out1 + (size_t)(v - 20000) * 256;
        Kd = 256; lse = g_lse[2 * B_ROWS + b]; extra = g_tail[b * 4 + 1] - hlse;
    } else if (v < 80000) {
        a = g_h2 + (size_t)b * 128; w = out2 + (size_t)(v - 40000) * 128;
        Kd = 128; lse = g_lse[3 * B_ROWS + b]; extra = g_tail[b * 4 + 2] - hlse;
    } else {
        a = g_h3 + (size_t)b * 64; w = out3 + (size_t)(v - 80000) * 64;
        Kd = 64; lse = g_lse[4 * B_ROWS + b]; extra = g_tail[b * 4 + 3] - hlse;
    }

    float dot = 0.f;
    for (int k = lane * 4; k < Kd; k += 128) {
        float4 av = *(const float4*)(a + k);
        float4 wv = *(const float4*)(w + k);
        dot += av.x * wv.x + av.y * wv.y + av.z * wv.z + av.w * wv.w;
    }
#pragma unroll
    for (int o = 16; o >= 1; o >>= 1) dot += __shfl_xor_sync(0xffffffffu, dot, o);

    if (lane == 0) {
        float lp = dot - lse + extra;
        float wt = (1.f - discard[v]) * mk;
        atomicAdd(&g_num[b], -lp * wt);
        atomicAdd(&g_den[b], wt);
    }
}

// ----------------------------------------------------------------------------
__global__ void final_kernel(float* out) {
    __shared__ float red[256];
    float s = 0.f;
    for (int i = threadIdx.x; i < B_ROWS; i += 256) s += g_num[i] / g_den[i];
    red[threadIdx.x] = s;
    __syncthreads();
    for (int o = 128; o >= 1; o >>= 1) {
        if (threadIdx.x < o) red[threadIdx.x] += red[threadIdx.x + o];
        __syncthreads();
    }
    if (threadIdx.x == 0)
        out[0] = (float)((double)red[0] / (1024.0 + 1e-5));
}

// ============================================================================
extern "C" void kernel_launch(void* const* d_in, const int* in_sizes, int n_in,
                              void* d_out, int out_size)
{
    const float* feat    = (const float*)d_in[0];
    const float* headW   = (const float*)d_in[1];
    const float* proj0   = (const float*)d_in[2];
    const float* out0    = (const float*)d_in[3];
    const float* proj1   = (const float*)d_in[4];
    const float* out1    = (const float*)d_in[5];
    const float* proj2   = (const float*)d_in[6];
    const float* out2    = (const float*)d_in[7];
    const float* proj3   = (const float*)d_in[8];
    const float* out3    = (const float*)d_in[9];
    const float* discard = (const float*)d_in[10];
    const void*  tgt     = d_in[11];
    const void*  msk     = d_in[12];
    float* out = (float*)d_out;

    detect_kernel<<<1, 1>>>(tgt, msk);
    zero_kernel<<<4, 256>>>();

    // proj GEMMs: h_i = feat @ proj_i.T
    gemm_tile_kernel<0><<<dim3(8, 4), 256>>>(feat, proj0, 512, 1024, -1, 0);
    gemm_tile_kernel<0><<<dim3(8, 2), 256>>>(feat, proj1, 256, 1024, -1, 1);
    gemm_tile_kernel<0><<<dim3(8, 1), 256>>>(feat, proj2, 128, 1024, -1, 2);
    gemm_tile_kernel<0><<<dim3(8, 1), 256>>>(feat, proj3,  64, 1024, -1, 3);

    // GEMM + online LSE partials
    gemm_tile_kernel<1><<<dim3(8,  79), 256>>>(feat, headW, NHEAD, 1024, -1, 0);
    gemm_tile_kernel<1><<<dim3(8,  79), 256>>>(nullptr, out0, 10000, 512, 0, 1);
    gemm_tile_kernel<1><<<dim3(8, 157), 256>>>(nullptr, out1, 20000, 256, 1, 2);
    gemm_tile_kernel<1><<<dim3(8, 313), 256>>>(nullptr, out2, 40000, 128, 2, 3);
    gemm_tile_kernel<1><<<dim3(8, 157), 256>>>(nullptr, out3, 20000,  64, 3, 4);

    combine_kernel<<<dim3(1024, 5), 32>>>();

    loss_kernel<<<16384, 256>>>(feat, headW, out0, out1, out2, out3,
                                discard, tgt, msk);

    final_kernel<<<1, 256>>>(out);
}

// round 4
// speedup vs baseline: 4.2111x; 4.2111x over previous
#include <cuda_runtime.h>
#include <cuda_bf16.h>
#include <cstdint>
#include <math.h>

// ============================================================================
// AdaptiveLoss via mma.sync bf16 tensor cores (arch-neutral PTX, works on the
// compute_103 virtual target). No [B,VOCAB] materialization: GEMM + fused
// online LSE per 128-col chunk, then per-target gather.
// ============================================================================

#define B_ROWS 1024
#define ROWB   144        // padded SMEM row bytes (64 bf16 = 128B + 16B pad)
#define STG    36864      // per pipeline stage: A 18432 + B 18432
#define SMEM_SZ (2 * STG) // 73728

// 128-col LSE chunks
__device__ const int d_chunks[5] = {79, 79, 157, 313, 157};
__device__ const int d_pbase[5]  = {0, 80896, 161792, 322560, 643072};
#define PM_TOTAL 803840

// fp32 scratch
__device__ float g_h0[B_ROWS * 512];
__device__ float g_h1[B_ROWS * 256];
__device__ float g_h2[B_ROWS * 128];
__device__ float g_h3[B_ROWS * 64];
__device__ float g_pm[PM_TOTAL];
__device__ float g_ps[PM_TOTAL];
__device__ float g_lse[5 * B_ROWS];
__device__ float g_tail[B_ROWS * 4];
__device__ float g_num[B_ROWS];
__device__ float g_den[B_ROWS];
__device__ int   g_flags[2];

// bf16 operand buffers
__device__ __nv_bfloat16 bf_feat[B_ROWS * 1024];
__device__ __nv_bfloat16 bf_headW[10244096];
__device__ __nv_bfloat16 bf_out0[5120000];
__device__ __nv_bfloat16 bf_out1[5120000];
__device__ __nv_bfloat16 bf_out2[5120000];
__device__ __nv_bfloat16 bf_out3[1280000];
__device__ __nv_bfloat16 bf_h0[B_ROWS * 512];
__device__ __nv_bfloat16 bf_h1[B_ROWS * 256];
__device__ __nv_bfloat16 bf_h2[B_ROWS * 128];
__device__ __nv_bfloat16 bf_h3[B_ROWS * 64];

// ---------------------------------------------------------------- PTX helpers
__device__ __forceinline__ uint32_t smem_u32(const void* p) {
    uint32_t a;
    asm("{ .reg .u64 t; cvta.to.shared.u64 t, %1; cvt.u32.u64 %0, t; }"
        : "=r"(a) : "l"(p));
    return a;
}
__device__ __forceinline__ void cp16(uint32_t dst, const void* src, int szbytes) {
    asm volatile("cp.async.cg.shared.global [%0], [%1], 16, %2;"
                 :: "r"(dst), "l"(src), "r"(szbytes) : "memory");
}
#define CP_COMMIT() asm volatile("cp.async.commit_group;" ::: "memory")
#define CP_WAIT1()  asm volatile("cp.async.wait_group 1;" ::: "memory")

__device__ __forceinline__ void ldsm_x4(uint32_t* r, uint32_t addr) {
    asm volatile("ldmatrix.sync.aligned.m8n8.x4.shared.b16 {%0,%1,%2,%3}, [%4];"
                 : "=r"(r[0]), "=r"(r[1]), "=r"(r[2]), "=r"(r[3]) : "r"(addr));
}
__device__ __forceinline__ void mma_bf16(float* c, const uint32_t* a,
                                         const uint32_t* b) {
    asm volatile(
        "mma.sync.aligned.m16n8k16.row.col.f32.bf16.bf16.f32 "
        "{%0,%1,%2,%3}, {%4,%5,%6,%7}, {%8,%9}, {%0,%1,%2,%3};"
        : "+f"(c[0]), "+f"(c[1]), "+f"(c[2]), "+f"(c[3])
        : "r"(a[0]), "r"(a[1]), "r"(a[2]), "r"(a[3]), "r"(b[0]), "r"(b[1]));
}

// ============================================================================
// gemm_mma<MODE>: C[128,128] tile = A[128,K] @ W[N,K]^T  (bf16 in, fp32 acc)
// MODE 0: write C to g_h{outSel} (fp32) + bf_h{outSel} (bf16).
// MODE 1: fused online (max, sumexp) per row over this 128-col chunk;
//         outSel = matrix idx; head (0) captures tail logits 10000..10003.
// ============================================================================
template <int MODE>
__global__ __launch_bounds__(256, 2)
void gemm_mma(int N, int K, int aSel, int outSel)
{
    extern __shared__ char smem[];
    const uint32_t sb = smem_u32(smem);
    const int tid  = threadIdx.x;
    const int lane = tid & 31;
    const int wid  = tid >> 5;
    const int warpM = wid & 1;     // 2 x 64 rows
    const int warpN = wid >> 1;    // 4 x 32 cols

    const __nv_bfloat16* A =
        (aSel < 0) ? bf_feat :
        (aSel == 0) ? bf_h0 : (aSel == 1) ? bf_h1 :
        (aSel == 2) ? bf_h2 : bf_h3;
    const __nv_bfloat16* W =
        (outSel == 0 && MODE == 1) ? bf_headW :
        (MODE == 0) ? ((outSel == 0) ? bf_out0 : (outSel == 1) ? bf_out1
                     : (outSel == 2) ? bf_out2 : bf_out3)
                    : ((outSel == 1) ? bf_out0 : (outSel == 2) ? bf_out1
                     : (outSel == 3) ? bf_out2 : bf_out3);
    // NOTE: MODE 0 uses W = proj matrix passed through bf_out slots? No —
    // proj weights have their own buffers; handled via aSel/outSel contract:
    // for MODE 0 we pass the proj matrix pointer through the table below.

    const int rowBase = blockIdx.x * 128;
    const int colBase = blockIdx.y * 128;
    const int nch = K >> 6;            // 64-element K chunks

    float acc[4][4][4];
#pragma unroll
    for (int i = 0; i < 4; i++)
#pragma unroll
        for (int j = 0; j < 4; j++)
#pragma unroll
            for (int k = 0; k < 4; k++) acc[i][j][k] = 0.f;

    // per-thread ldmatrix address components
    const uint32_t aRowOff =
        (uint32_t)((warpM * 64 + ((lane >> 3) & 1) * 8 + (lane & 7)) * ROWB
                   + (lane >> 4) * 16);
    const uint32_t bRowOff =
        (uint32_t)((((lane >> 4) & 1) * 8 + (lane & 7)) * ROWB
                   + ((lane >> 3) & 1) * 16);

    // ---- cooperative chunk loader (cp.async) ----
    auto load_chunk = [&](int c, int buf) {
        const int k0 = c * 64;
        const uint32_t aB = sb + buf * STG;
        const uint32_t bB = aB + 18432;
#pragma unroll
        for (int i = 0; i < 4; i++) {
            const int t = tid + i * 256;          // 0..1023
            const int r = t >> 3, q = t & 7;
            cp16(aB + r * ROWB + q * 16,
                 A + (size_t)(rowBase + r) * K + k0 + q * 8, 16);
        }
#pragma unroll
        for (int i = 0; i < 4; i++) {
            const int t = tid + i * 256;
            const int r = t >> 3, q = t & 7;
            const int n = colBase + r;
            const int ok = (n < N) ? 16 : 0;
            const __nv_bfloat16* src =
                W + (size_t)(ok ? n : 0) * K + k0 + q * 8;
            cp16(bB + r * ROWB + q * 16, src, ok);
        }
    };

    load_chunk(0, 0);
    CP_COMMIT();
    for (int c = 0; c < nch; c++) {
        __syncthreads();
        if (c + 1 < nch) load_chunk(c + 1, (c + 1) & 1);
        CP_COMMIT();
        CP_WAIT1();
        __syncthreads();
        const uint32_t aB = sb + (c & 1) * STG;
        const uint32_t bB = aB + 18432;
#pragma unroll
        for (int ks = 0; ks < 4; ks++) {
            uint32_t af[4][4], bfr[2][4];
#pragma unroll
            for (int mt = 0; mt < 4; mt++)
                ldsm_x4(af[mt], aB + aRowOff + mt * (16 * ROWB) + ks * 32);
#pragma unroll
            for (int p = 0; p < 2; p++)
                ldsm_x4(bfr[p], bB + (warpN * 32 + p * 16) * ROWB + bRowOff + ks * 32);
#pragma unroll
            for (int mt = 0; mt < 4; mt++)
#pragma unroll
                for (int nt = 0; nt < 4; nt++)
                    mma_bf16(acc[mt][nt], af[mt], &bfr[nt >> 1][(nt & 1) * 2]);
        }
    }
    __syncthreads();   // smem free for epilogue scratch

    if (MODE == 0) {
        float* Cf = (outSel == 0) ? g_h0 : (outSel == 1) ? g_h1
                  : (outSel == 2) ? g_h2 : g_h3;
        __nv_bfloat16* Cb = (outSel == 0) ? bf_h0 : (outSel == 1) ? bf_h1
                          : (outSel == 2) ? bf_h2 : bf_h3;
#pragma unroll
        for (int mt = 0; mt < 4; mt++)
#pragma unroll
            for (int nt = 0; nt < 4; nt++)
#pragma unroll
                for (int rg = 0; rg < 4; rg++) {
                    const int r = rowBase + warpM * 64 + mt * 16 + (lane >> 2)
                                + (rg >> 1) * 8;
                    const int cc = colBase + warpN * 32 + nt * 8
                                 + (lane & 3) * 2 + (rg & 1);
                    if (cc < N) {
                        const float v = acc[mt][nt][rg];
                        Cf[(size_t)r * N + cc] = v;
                        Cb[(size_t)r * N + cc] = __float2bfloat16(v);
                    }
                }
    } else {
        float* smM = (float*)smem;          // 128 rows x 4 warpN
        float* smS = (float*)smem + 512;
#pragma unroll
        for (int mt = 0; mt < 4; mt++)
#pragma unroll
            for (int hf = 0; hf < 2; hf++) {
                const int rl = warpM * 64 + mt * 16 + (lane >> 2) + hf * 8;
                const int rg = rowBase + rl;
                float m = -INFINITY;
#pragma unroll
                for (int nt = 0; nt < 4; nt++)
#pragma unroll
                    for (int b = 0; b < 2; b++) {
                        const int cc = colBase + warpN * 32 + nt * 8
                                     + (lane & 3) * 2 + b;
                        if (cc < N) m = fmaxf(m, acc[mt][nt][hf * 2 + b]);
                    }
                float s = 0.f;
                if (m > -INFINITY) {
#pragma unroll
                    for (int nt = 0; nt < 4; nt++)
#pragma unroll
                        for (int b = 0; b < 2; b++) {
                            const int cc = colBase + warpN * 32 + nt * 8
                                         + (lane & 3) * 2 + b;
                            if (cc < N) {
                                const float v = acc[mt][nt][hf * 2 + b];
                                s += expf(v - m);
                                if (outSel == 0 && cc >= 10000)
                                    g_tail[rg * 4 + (cc - 10000)] = v;
                            }
                        }
                }
#pragma unroll
                for (int o = 1; o <= 2; o <<= 1) {
                    const float mo = __shfl_xor_sync(0xffffffffu, m, o);
                    const float so = __shfl_xor_sync(0xffffffffu, s, o);
                    const float M2 = fmaxf(m, mo);
                    if (M2 == -INFINITY) { m = M2; s = 0.f; }
                    else { s = s * expf(m - M2) + so * expf(mo - M2); m = M2; }
                }
                if ((lane & 3) == 0) {
                    smM[rl * 4 + warpN] = m;
                    smS[rl * 4 + warpN] = s;
                }
            }
        __syncthreads();
        if (tid < 128) {
            float m = -INFINITY, s = 0.f;
#pragma unroll
            for (int w = 0; w < 4; w++) {
                const float mo = smM[tid * 4 + w], so = smS[tid * 4 + w];
                const float M2 = fmaxf(m, mo);
                if (M2 == -INFINITY) { m = M2; s = 0.f; }
                else { s = s * expf(m - M2) + so * expf(mo - M2); m = M2; }
            }
            const int chunks = d_chunks[outSel];
            const size_t o = d_pbase[outSel]
                           + (size_t)(rowBase + tid) * chunks + blockIdx.y;
            g_pm[o] = m; g_ps[o] = s;
        }
    }
}

// MODE 0 needs proj weights as W; route them through dedicated bf buffers:
__device__ __nv_bfloat16 bf_proj0[512 * 1024];
__device__ __nv_bfloat16 bf_proj1[256 * 1024];
__device__ __nv_bfloat16 bf_proj2[128 * 1024];
__device__ __nv_bfloat16 bf_proj3[64 * 1024];

// Specialized proj GEMM (MODE 0) using bf_proj* as W.
__global__ __launch_bounds__(256, 2)
void gemm_proj(int N, int K, int outSel)
{
    extern __shared__ char smem[];
    const uint32_t sb = smem_u32(smem);
    const int tid = threadIdx.x, lane = tid & 31, wid = tid >> 5;
    const int warpM = wid & 1, warpN = wid >> 1;
    const __nv_bfloat16* A = bf_feat;
    const __nv_bfloat16* W = (outSel == 0) ? bf_proj0 : (outSel == 1) ? bf_proj1
                           : (outSel == 2) ? bf_proj2 : bf_proj3;
    const int rowBase = blockIdx.x * 128;
    const int colBase = blockIdx.y * 128;
    const int nch = K >> 6;

    float acc[4][4][4];
#pragma unroll
    for (int i = 0; i < 4; i++)
#pragma unroll
        for (int j = 0; j < 4; j++)
#pragma unroll
            for (int k = 0; k < 4; k++) acc[i][j][k] = 0.f;

    const uint32_t aRowOff =
        (uint32_t)((warpM * 64 + ((lane >> 3) & 1) * 8 + (lane & 7)) * ROWB
                   + (lane >> 4) * 16);
    const uint32_t bRowOff =
        (uint32_t)((((lane >> 4) & 1) * 8 + (lane & 7)) * ROWB
                   + ((lane >> 3) & 1) * 16);

    auto load_chunk = [&](int c, int buf) {
        const int k0 = c * 64;
        const uint32_t aB = sb + buf * STG, bB = aB + 18432;
#pragma unroll
        for (int i = 0; i < 4; i++) {
            const int t = tid + i * 256, r = t >> 3, q = t & 7;
            cp16(aB + r * ROWB + q * 16,
                 A + (size_t)(rowBase + r) * K + k0 + q * 8, 16);
        }
#pragma unroll
        for (int i = 0; i < 4; i++) {
            const int t = tid + i * 256, r = t >> 3, q = t & 7;
            const int n = colBase + r;
            const int ok = (n < N) ? 16 : 0;
            cp16(bB + r * ROWB + q * 16,
                 W + (size_t)(ok ? n : 0) * K + k0 + q * 8, ok);
        }
    };

    load_chunk(0, 0);
    CP_COMMIT();
    for (int c = 0; c < nch; c++) {
        __syncthreads();
        if (c + 1 < nch) load_chunk(c + 1, (c + 1) & 1);
        CP_COMMIT();
        CP_WAIT1();
        __syncthreads();
        const uint32_t aB = sb + (c & 1) * STG, bB = aB + 18432;
#pragma unroll
        for (int ks = 0; ks < 4; ks++) {
            uint32_t af[4][4], bfr[2][4];
#pragma unroll
            for (int mt = 0; mt < 4; mt++)
                ldsm_x4(af[mt], aB + aRowOff + mt * (16 * ROWB) + ks * 32);
#pragma unroll
            for (int p = 0; p < 2; p++)
                ldsm_x4(bfr[p], bB + (warpN * 32 + p * 16) * ROWB + bRowOff + ks * 32);
#pragma unroll
            for (int mt = 0; mt < 4; mt++)
#pragma unroll
                for (int nt = 0; nt < 4; nt++)
                    mma_bf16(acc[mt][nt], af[mt], &bfr[nt >> 1][(nt & 1) * 2]);
        }
    }
    __syncthreads();

    float* Cf = (outSel == 0) ? g_h0 : (outSel == 1) ? g_h1
              : (outSel == 2) ? g_h2 : g_h3;
    __nv_bfloat16* Cb = (outSel == 0) ? bf_h0 : (outSel == 1) ? bf_h1
                      : (outSel == 2) ? bf_h2 : bf_h3;
#pragma unroll
    for (int mt = 0; mt < 4; mt++)
#pragma unroll
        for (int nt = 0; nt < 4; nt++)
#pragma unroll
            for (int rg = 0; rg < 4; rg++) {
                const int r = rowBase + warpM * 64 + mt * 16 + (lane >> 2)
                            + (rg >> 1) * 8;
                const int cc = colBase + warpN * 32 + nt * 8
                             + (lane & 3) * 2 + (rg & 1);
                if (cc < N) {
                    const float v = acc[mt][nt][rg];
                    Cf[(size_t)r * N + cc] = v;
                    Cb[(size_t)r * N + cc] = __float2bfloat16(v);
                }
            }
}

// ---------------------------------------------------------------- cvt + misc
__global__ void cvt_kernel(const float* __restrict__ s,
                           __nv_bfloat16* __restrict__ d, int n) {
    const int i = (blockIdx.x * blockDim.x + threadIdx.x) * 4;
    if (i < n) {
        const float4 v = *(const float4*)(s + i);
        __nv_bfloat162* p = (__nv_bfloat162*)(d + i);
        p[0] = __floats2bfloat162_rn(v.x, v.y);
        p[1] = __floats2bfloat162_rn(v.z, v.w);
    }
}

__global__ void detect_kernel(const void* tgt, const void* msk) {
    const int* ti = (const int*)tgt;
    int nz = 0;
    for (int j = 0; j < 128; j++) nz += (ti[2 * j + 1] != 0);
    g_flags[0] = (nz <= 8) ? 1 : 0;
    const unsigned int* mw = (const unsigned int*)msk;
    int looks_i32 = 1;
    for (int j = 0; j < 64; j++) if (mw[j] > 255u) looks_i32 = 0;
    g_flags[1] = looks_i32;
}

__global__ void zero_kernel() {
    int i = blockIdx.x * blockDim.x + threadIdx.x;
    if (i < B_ROWS) { g_num[i] = 0.f; g_den[i] = 0.f; }
}

__global__ void combine_kernel() {
    int row = blockIdx.x, mat = blockIdx.y, lane = threadIdx.x;
    int chunks = d_chunks[mat];
    const float* pm = g_pm + d_pbase[mat] + (size_t)row * chunks;
    const float* ps = g_ps + d_pbase[mat] + (size_t)row * chunks;
    float m = -INFINITY, s = 0.f;
    for (int c = lane; c < chunks; c += 32) {
        float mo = pm[c], so = ps[c];
        float M2 = fmaxf(m, mo);
        if (M2 == -INFINITY) { m = M2; s = 0.f; }
        else { s = s * expf(m - M2) + so * expf(mo - M2); m = M2; }
    }
    for (int o = 1; o < 32; o <<= 1) {
        float mo = __shfl_xor_sync(0xffffffffu, m, o);
        float so = __shfl_xor_sync(0xffffffffu, s, o);
        float M2 = fmaxf(m, mo);
        if (M2 == -INFINITY) { m = M2; s = 0.f; }
        else { s = s * expf(m - M2) + so * expf(mo - M2); m = M2; }
    }
    if (lane == 0) g_lse[mat * B_ROWS + row] = m + logf(s);
}

__global__ void loss_kernel(const float* __restrict__ feat,
                            const float* __restrict__ headW,
                            const float* __restrict__ out0,
                            const float* __restrict__ out1,
                            const float* __restrict__ out2,
                            const float* __restrict__ out3,
                            const float* __restrict__ discard,
                            const void* __restrict__ tgt,
                            const void* __restrict__ msk)
{
    int gwarp = (blockIdx.x * blockDim.x + threadIdx.x) >> 5;
    int lane  = threadIdx.x & 31;
    if (gwarp >= B_ROWS * 128) return;
    int b = gwarp >> 7;

    long long v;
    if (g_flags[0]) v = ((const long long*)tgt)[gwarp];
    else            v = (long long)((const int*)tgt)[gwarp];

    float mk;
    if (g_flags[1]) mk = (((const int*)msk)[gwarp] != 0) ? 1.f : 0.f;
    else            mk = (((const unsigned char*)msk)[gwarp] != 0) ? 1.f : 0.f;

    const float *a, *w;
    int Kd; float lse, extra;
    float hlse = g_lse[b];
    if (v < 10000) {
        a = feat + (size_t)b * 1024; w = headW + (size_t)v * 1024;
        Kd = 1024; lse = hlse; extra = 0.f;
    } else if (v < 20000) {
        a = g_h0 + (size_t)b * 512; w = out0 + (size_t)(v - 10000) * 512;
        Kd = 512; lse = g_lse[1 * B_ROWS + b]; extra = g_tail[b * 4 + 0] - hlse;
    } else if (v < 40000) {
        a = g_h1 + (size_t)b * 256; w = out1 + (size_t)(v - 20000) * 256;
        Kd = 256; lse = g_lse[2 * B_ROWS + b]; extra = g_tail[b * 4 + 1] - hlse;
    } else if (v < 80000) {
        a = g_h2 + (size_t)b * 128; w = out2 + (size_t)(v - 40000) * 128;
        Kd = 128; lse = g_lse[3 * B_ROWS + b]; extra = g_tail[b * 4 + 2] - hlse;
    } else {
        a = g_h3 + (size_t)b * 64; w = out3 + (size_t)(v - 80000) * 64;
        Kd = 64; lse = g_lse[4 * B_ROWS + b]; extra = g_tail[b * 4 + 3] - hlse;
    }

    float dot = 0.f;
    for (int k = lane * 4; k < Kd; k += 128) {
        float4 av = *(const float4*)(a + k);
        float4 wv = *(const float4*)(w + k);
        dot += av.x * wv.x + av.y * wv.y + av.z * wv.z + av.w * wv.w;
    }
#pragma unroll
    for (int o = 16; o >= 1; o >>= 1) dot += __shfl_xor_sync(0xffffffffu, dot, o);

    if (lane == 0) {
        float lp = dot - lse + extra;
        float wt = (1.f - discard[v]) * mk;
        atomicAdd(&g_num[b], -lp * wt);
        atomicAdd(&g_den[b], wt);
    }
}

__global__ void final_kernel(float* out) {
    __shared__ float red[256];
    float s = 0.f;
    for (int i = threadIdx.x; i < B_ROWS; i += 256) s += g_num[i] / g_den[i];
    red[threadIdx.x] = s;
    __syncthreads();
    for (int o = 128; o >= 1; o >>= 1) {
        if (threadIdx.x < o) red[threadIdx.x] += red[threadIdx.x + o];
        __syncthreads();
    }
    if (threadIdx.x == 0)
        out[0] = (float)((double)red[0] / (1024.0 + 1e-5));
}

// ============================================================================
extern "C" void kernel_launch(void* const* d_in, const int* in_sizes, int n_in,
                              void* d_out, int out_size)
{
    const float* feat    = (const float*)d_in[0];
    const float* headW   = (const float*)d_in[1];
    const float* proj0   = (const float*)d_in[2];
    const float* out0    = (const float*)d_in[3];
    const float* proj1   = (const float*)d_in[4];
    const float* out1    = (const float*)d_in[5];
    const float* proj2   = (const float*)d_in[6];
    const float* out2    = (const float*)d_in[7];
    const float* proj3   = (const float*)d_in[8];
    const float* out3    = (const float*)d_in[9];
    const float* discard = (const float*)d_in[10];
    const void*  tgt     = d_in[11];
    const void*  msk     = d_in[12];
    float* out = (float*)d_out;

    cudaFuncSetAttribute(gemm_mma<1>, cudaFuncAttributeMaxDynamicSharedMemorySize, SMEM_SZ);
    cudaFuncSetAttribute(gemm_proj,  cudaFuncAttributeMaxDynamicSharedMemorySize, SMEM_SZ);

    detect_kernel<<<1, 1>>>(tgt, msk);
    zero_kernel<<<4, 256>>>();

    // fp32 -> bf16 conversions
    __nv_bfloat16 *p_feat, *p_headW, *p_o0, *p_o1, *p_o2, *p_o3;
    __nv_bfloat16 *p_p0, *p_p1, *p_p2, *p_p3;
    cudaGetSymbolAddress((void**)&p_feat,  bf_feat);
    cudaGetSymbolAddress((void**)&p_headW, bf_headW);
    cudaGetSymbolAddress((void**)&p_o0, bf_out0);
    cudaGetSymbolAddress((void**)&p_o1, bf_out1);
    cudaGetSymbolAddress((void**)&p_o2, bf_out2);
    cudaGetSymbolAddress((void**)&p_o3, bf_out3);
    cudaGetSymbolAddress((void**)&p_p0, bf_proj0);
    cudaGetSymbolAddress((void**)&p_p1, bf_proj1);
    cudaGetSymbolAddress((void**)&p_p2, bf_proj2);
    cudaGetSymbolAddress((void**)&p_p3, bf_proj3);

    cvt_kernel<<<1024, 256>>>(feat, p_feat, 1048576);
    cvt_kernel<<<10004, 256>>>(headW, p_headW, 10244096);
    cvt_kernel<<<5000, 256>>>(out0, p_o0, 5120000);
    cvt_kernel<<<5000, 256>>>(out1, p_o1, 5120000);
    cvt_kernel<<<5000, 256>>>(out2, p_o2, 5120000);
    cvt_kernel<<<1250, 256>>>(out3, p_o3, 1280000);
    cvt_kernel<<<512, 256>>>(proj0, p_p0, 524288);
    cvt_kernel<<<256, 256>>>(proj1, p_p1, 262144);
    cvt_kernel<<<128, 256>>>(proj2, p_p2, 131072);
    cvt_kernel<<<64, 256>>>(proj3, p_p3, 65536);

    // proj GEMMs: h_i = feat @ proj_i.T  (fp32 + bf16 outputs)
    gemm_proj<<<dim3(8, 4), 256, SMEM_SZ>>>(512, 1024, 0);
    gemm_proj<<<dim3(8, 2), 256, SMEM_SZ>>>(256, 1024, 1);
    gemm_proj<<<dim3(8, 1), 256, SMEM_SZ>>>(128, 1024, 2);
    gemm_proj<<<dim3(8, 1), 256, SMEM_SZ>>>(64, 1024, 3);

    // GEMM + online LSE partials (128-col chunks)
    gemm_mma<1><<<dim3(8,  79), 256, SMEM_SZ>>>(10004, 1024, -1, 0);
    gemm_mma<1><<<dim3(8,  79), 256, SMEM_SZ>>>(10000,  512,  0, 1);
    gemm_mma<1><<<dim3(8, 157), 256, SMEM_SZ>>>(20000,  256,  1, 2);
    gemm_mma<1><<<dim3(8, 313), 256, SMEM_SZ>>>(40000,  128,  2, 3);
    gemm_mma<1><<<dim3(8, 157), 256, SMEM_SZ>>>(20000,   64,  3, 4);

    combine_kernel<<<dim3(1024, 5), 32>>>();

    loss_kernel<<<16384, 256>>>(feat, headW, out0, out1, out2, out3,
                                discard, tgt, msk);

    final_kernel<<<1, 256>>>(out);
}

// round 5
// speedup vs baseline: 5.4492x; 1.2940x over previous
#include <cuda_runtime.h>
#include <cuda_bf16.h>
#include <cstdint>
#include <math.h>

// ============================================================================
// AdaptiveLoss via mma.sync bf16 (arch-neutral PTX). Fused-launch edition:
//  1. init (dtype detect + zero)
//  2. cvt_all: fp32->bf16 for all operands, one launch
//  3. proj:    4 proj GEMMs in one launch          (writes bf16 h_i)
//  4. lse:     head + 4 cluster GEMM+online-LSE in one launch (grid y=395)
//  5. combine -> per-row LSE     6. loss gather (bf16)     7. final
// GEMM tile: 128x256, 512 thr, 16 warps (32x64/warp), K-chunk 64, 2-stage
// cp.async, 144B-padded rows.
// ============================================================================

#define B_ROWS 1024
#define ROWB   144
#define SMEM_SZ 110592   // A: 2*128*144 = 36864, B: 2*256*144 = 73728

// 256-col LSE chunks: head 40, c0 40, c1 79, c2 157, c3 79
__device__ const int d_chunks[5] = {40, 40, 79, 157, 79};
__device__ const int d_pbase[5]  = {0, 40960, 81920, 162816, 323584};
#define PM_TOTAL 404480

__device__ float g_pm[PM_TOTAL];
__device__ float g_ps[PM_TOTAL];
__device__ float g_lse[5 * B_ROWS];
__device__ float g_tail[B_ROWS * 4];
__device__ float g_num[B_ROWS];
__device__ float g_den[B_ROWS];
__device__ int   g_flags[2];

__device__ __nv_bfloat16 bf_feat[B_ROWS * 1024];
__device__ __nv_bfloat16 bf_headW[10244096];
__device__ __nv_bfloat16 bf_out0[5120000];
__device__ __nv_bfloat16 bf_out1[5120000];
__device__ __nv_bfloat16 bf_out2[5120000];
__device__ __nv_bfloat16 bf_out3[1280000];
__device__ __nv_bfloat16 bf_proj0[512 * 1024];
__device__ __nv_bfloat16 bf_proj1[256 * 1024];
__device__ __nv_bfloat16 bf_proj2[128 * 1024];
__device__ __nv_bfloat16 bf_proj3[64 * 1024];
__device__ __nv_bfloat16 bf_h0[B_ROWS * 512];
__device__ __nv_bfloat16 bf_h1[B_ROWS * 256];
__device__ __nv_bfloat16 bf_h2[B_ROWS * 128];
__device__ __nv_bfloat16 bf_h3[B_ROWS * 64];

// ---------------------------------------------------------------- PTX helpers
__device__ __forceinline__ uint32_t smem_u32(const void* p) {
    uint32_t a;
    asm("{ .reg .u64 t; cvta.to.shared.u64 t, %1; cvt.u32.u64 %0, t; }"
        : "=r"(a) : "l"(p));
    return a;
}
__device__ __forceinline__ void cp16(uint32_t dst, const void* src, int szbytes) {
    asm volatile("cp.async.cg.shared.global [%0], [%1], 16, %2;"
                 :: "r"(dst), "l"(src), "r"(szbytes) : "memory");
}
#define CP_COMMIT() asm volatile("cp.async.commit_group;" ::: "memory")
#define CP_WAIT1()  asm volatile("cp.async.wait_group 1;" ::: "memory")

__device__ __forceinline__ void ldsm_x4(uint32_t* r, uint32_t addr) {
    asm volatile("ldmatrix.sync.aligned.m8n8.x4.shared.b16 {%0,%1,%2,%3}, [%4];"
                 : "=r"(r[0]), "=r"(r[1]), "=r"(r[2]), "=r"(r[3]) : "r"(addr));
}
__device__ __forceinline__ void mma_bf16(float* c, const uint32_t* a,
                                         const uint32_t* b) {
    asm volatile(
        "mma.sync.aligned.m16n8k16.row.col.f32.bf16.bf16.f32 "
        "{%0,%1,%2,%3}, {%4,%5,%6,%7}, {%8,%9}, {%0,%1,%2,%3};"
        : "+f"(c[0]), "+f"(c[1]), "+f"(c[2]), "+f"(c[3])
        : "r"(a[0]), "r"(a[1]), "r"(a[2]), "r"(a[3]), "r"(b[0]), "r"(b[1]));
}

// ============================================================================
// Core 128x256 GEMM tile: C = A[128,K] @ W[N,K]^T, bf16 in / fp32 acc.
// MODE 0: write bf16 C into Cb.  MODE 1: fused online (max,sumexp) per row
// over this 256-col chunk; sel = matrix idx (0=head captures tail logits).
// ============================================================================
template <int MODE>
__device__ __forceinline__ void gemm_core(
    const __nv_bfloat16* __restrict__ A, const __nv_bfloat16* __restrict__ W,
    __nv_bfloat16* __restrict__ Cb,
    int N, int K, int rowBase, int colBase, int sel, int ytile, char* smem)
{
    const uint32_t sb = smem_u32(smem);
    const int tid  = threadIdx.x;
    const int lane = tid & 31;
    const int wid  = tid >> 5;
    const int warpM = wid & 3;     // 4 x 32 rows
    const int warpN = wid >> 2;    // 4 x 64 cols

    float acc[2][8][4];
#pragma unroll
    for (int i = 0; i < 2; i++)
#pragma unroll
        for (int j = 0; j < 8; j++)
#pragma unroll
            for (int k = 0; k < 4; k++) acc[i][j][k] = 0.f;

    const uint32_t aRowOff =
        (uint32_t)((warpM * 32 + ((lane >> 3) & 1) * 8 + (lane & 7)) * ROWB
                   + (lane >> 4) * 16);
    const uint32_t bRowOff =
        (uint32_t)((((lane >> 4) & 1) * 8 + (lane & 7)) * ROWB
                   + ((lane >> 3) & 1) * 16);

    auto load_chunk = [&](int c, int buf) {
        const int k0 = c * 64;
        const uint32_t aB = sb + buf * 18432;
        const uint32_t bB = sb + 36864 + buf * 36864;
#pragma unroll
        for (int i = 0; i < 2; i++) {                 // A: 128 rows x 8 q
            const int t = tid + i * 512;
            const int r = t >> 3, q = t & 7;
            cp16(aB + r * ROWB + q * 16,
                 A + (size_t)(rowBase + r) * K + k0 + q * 8, 16);
        }
#pragma unroll
        for (int i = 0; i < 4; i++) {                 // B: 256 rows x 8 q
            const int t = tid + i * 512;
            const int r = t >> 3, q = t & 7;
            const int n = colBase + r;
            const int ok = (n < N) ? 16 : 0;
            cp16(bB + r * ROWB + q * 16,
                 W + (size_t)(ok ? n : 0) * K + k0 + q * 8, ok);
        }
    };

    const int nch = K >> 6;
    load_chunk(0, 0);
    CP_COMMIT();
    for (int c = 0; c < nch; c++) {
        __syncthreads();
        if (c + 1 < nch) load_chunk(c + 1, (c + 1) & 1);
        CP_COMMIT();
        CP_WAIT1();
        __syncthreads();
        const uint32_t aB = sb + (c & 1) * 18432;
        const uint32_t bB = sb + 36864 + (c & 1) * 36864;
#pragma unroll
        for (int ks = 0; ks < 4; ks++) {
            uint32_t af[2][4], bf4[4][4];
#pragma unroll
            for (int mt = 0; mt < 2; mt++)
                ldsm_x4(af[mt], aB + aRowOff + mt * (16 * ROWB) + ks * 32);
#pragma unroll
            for (int p = 0; p < 4; p++)
                ldsm_x4(bf4[p], bB + (warpN * 64 + p * 16) * ROWB + bRowOff + ks * 32);
#pragma unroll
            for (int mt = 0; mt < 2; mt++)
#pragma unroll
                for (int nt = 0; nt < 8; nt++)
                    mma_bf16(acc[mt][nt], af[mt], &bf4[nt >> 1][(nt & 1) * 2]);
        }
    }
    __syncthreads();

    if (MODE == 0) {
#pragma unroll
        for (int mt = 0; mt < 2; mt++)
#pragma unroll
            for (int nt = 0; nt < 8; nt++)
#pragma unroll
                for (int rg = 0; rg < 4; rg++) {
                    const int r = rowBase + warpM * 32 + mt * 16 + (lane >> 2)
                                + (rg >> 1) * 8;
                    const int cc = colBase + warpN * 64 + nt * 8
                                 + (lane & 3) * 2 + (rg & 1);
                    if (cc < N)
                        Cb[(size_t)r * N + cc] = __float2bfloat16(acc[mt][nt][rg]);
                }
    } else {
        float* smM = (float*)smem;          // [128 rows][4 warpN]
        float* smS = (float*)smem + 512;
#pragma unroll
        for (int mt = 0; mt < 2; mt++)
#pragma unroll
            for (int hf = 0; hf < 2; hf++) {
                const int rl = warpM * 32 + mt * 16 + (lane >> 2) + hf * 8;
                const int rg = rowBase + rl;
                float m = -INFINITY;
#pragma unroll
                for (int nt = 0; nt < 8; nt++)
#pragma unroll
                    for (int b2 = 0; b2 < 2; b2++) {
                        const int cc = colBase + warpN * 64 + nt * 8
                                     + (lane & 3) * 2 + b2;
                        if (cc < N) m = fmaxf(m, acc[mt][nt][hf * 2 + b2]);
                    }
                float s = 0.f;
                if (m > -INFINITY) {
#pragma unroll
                    for (int nt = 0; nt < 8; nt++)
#pragma unroll
                        for (int b2 = 0; b2 < 2; b2++) {
                            const int cc = colBase + warpN * 64 + nt * 8
                                         + (lane & 3) * 2 + b2;
                            if (cc < N) {
                                const float v = acc[mt][nt][hf * 2 + b2];
                                s += __expf(v - m);
                                if (sel == 0 && cc >= 10000)
                                    g_tail[rg * 4 + (cc - 10000)] = v;
                            }
                        }
                }
#pragma unroll
                for (int o = 1; o <= 2; o <<= 1) {
                    const float mo = __shfl_xor_sync(0xffffffffu, m, o);
                    const float so = __shfl_xor_sync(0xffffffffu, s, o);
                    const float M2 = fmaxf(m, mo);
                    if (M2 == -INFINITY) { m = M2; s = 0.f; }
                    else { s = s * __expf(m - M2) + so * __expf(mo - M2); m = M2; }
                }
                if ((lane & 3) == 0) {
                    smM[rl * 4 + warpN] = m;
                    smS[rl * 4 + warpN] = s;
                }
            }
        __syncthreads();
        if (tid < 128) {
            float m = -INFINITY, s = 0.f;
#pragma unroll
            for (int w = 0; w < 4; w++) {
                const float mo = smM[tid * 4 + w], so = smS[tid * 4 + w];
                const float M2 = fmaxf(m, mo);
                if (M2 == -INFINITY) { m = M2; s = 0.f; }
                else { s = s * __expf(m - M2) + so * __expf(mo - M2); m = M2; }
            }
            const int chunks = d_chunks[sel];
            const size_t o = d_pbase[sel]
                           + (size_t)(rowBase + tid) * chunks + ytile;
            g_pm[o] = m; g_ps[o] = s;
        }
    }
}

// proj: y in [0,5): {proj0 tile0, proj0 tile1, proj1, proj2, proj3}
__global__ __launch_bounds__(512, 1)
void proj_kernel()
{
    extern __shared__ char smem[];
    const int y = blockIdx.y;
    const __nv_bfloat16* W;
    __nv_bfloat16* Cb;
    int N, colBase;
    if (y < 2)      { W = bf_proj0; Cb = bf_h0; N = 512; colBase = y * 256; }
    else if (y == 2){ W = bf_proj1; Cb = bf_h1; N = 256; colBase = 0; }
    else if (y == 3){ W = bf_proj2; Cb = bf_h2; N = 128; colBase = 0; }
    else            { W = bf_proj3; Cb = bf_h3; N = 64;  colBase = 0; }
    gemm_core<0>(bf_feat, W, Cb, N, 1024, blockIdx.x * 128, colBase, -1, 0, smem);
}

// lse: y in [0,395): head 40 | c0 40 | c1 79 | c2 157 | c3 79
__global__ __launch_bounds__(512, 1)
void lse_kernel()
{
    extern __shared__ char smem[];
    const int y = blockIdx.y;
    const __nv_bfloat16 *A, *W;
    int N, K, sel, ytile;
    if (y < 40)       { sel = 0; ytile = y;       A = bf_feat; W = bf_headW; N = 10004; K = 1024; }
    else if (y < 80)  { sel = 1; ytile = y - 40;  A = bf_h0;   W = bf_out0;  N = 10000; K = 512; }
    else if (y < 159) { sel = 2; ytile = y - 80;  A = bf_h1;   W = bf_out1;  N = 20000; K = 256; }
    else if (y < 316) { sel = 3; ytile = y - 159; A = bf_h2;   W = bf_out2;  N = 40000; K = 128; }
    else              { sel = 4; ytile = y - 316; A = bf_h3;   W = bf_out3;  N = 20000; K = 64; }
    gemm_core<1>(A, W, nullptr, N, K, blockIdx.x * 128, ytile * 256, sel, ytile, smem);
}

// ---------------------------------------------------------------- cvt (fused)
__global__ void cvt_all(const float* s0, const float* s1, const float* s2,
                        const float* s3, const float* s4, const float* s5,
                        const float* s6, const float* s7, const float* s8,
                        const float* s9)
{
    const int cum[11] = {0, 262144, 2823168, 4103168, 5383168, 6663168,
                         6983168, 7114240, 7179776, 7212544, 7228928};
    for (int i = blockIdx.x * blockDim.x + threadIdx.x; i < 7228928;
         i += gridDim.x * blockDim.x) {
        int seg = 0;
#pragma unroll
        for (int t = 1; t < 10; t++) seg += (i >= cum[t]);
        const int off = i - cum[seg];
        const float* src;
        __nv_bfloat16* dst;
        switch (seg) {
            case 0: src = s0; dst = bf_feat;  break;
            case 1: src = s1; dst = bf_headW; break;
            case 2: src = s2; dst = bf_out0;  break;
            case 3: src = s3; dst = bf_out1;  break;
            case 4: src = s4; dst = bf_out2;  break;
            case 5: src = s5; dst = bf_out3;  break;
            case 6: src = s6; dst = bf_proj0; break;
            case 7: src = s7; dst = bf_proj1; break;
            case 8: src = s8; dst = bf_proj2; break;
            default: src = s9; dst = bf_proj3; break;
        }
        const float4 v = ((const float4*)src)[off];
        __nv_bfloat162* p = (__nv_bfloat162*)dst + off * 2;
        p[0] = __floats2bfloat162_rn(v.x, v.y);
        p[1] = __floats2bfloat162_rn(v.z, v.w);
    }
}

// ---------------------------------------------------------------- small kernels
__global__ void init_kernel(const void* tgt, const void* msk) {
    const int tid = threadIdx.x;
    if (tid < B_ROWS) { g_num[tid] = 0.f; g_den[tid] = 0.f; }
    if (tid == 0) {
        const int* ti = (const int*)tgt;
        int nz = 0;
        for (int j = 0; j < 128; j++) nz += (ti[2 * j + 1] != 0);
        g_flags[0] = (nz <= 8) ? 1 : 0;
        const unsigned int* mw = (const unsigned int*)msk;
        int looks_i32 = 1;
        for (int j = 0; j < 64; j++) if (mw[j] > 255u) looks_i32 = 0;
        g_flags[1] = looks_i32;
    }
}

__global__ void combine_kernel() {
    int row = blockIdx.x, mat = blockIdx.y, lane = threadIdx.x;
    int chunks = d_chunks[mat];
    const float* pm = g_pm + d_pbase[mat] + (size_t)row * chunks;
    const float* ps = g_ps + d_pbase[mat] + (size_t)row * chunks;
    float m = -INFINITY, s = 0.f;
    for (int c = lane; c < chunks; c += 32) {
        float mo = pm[c], so = ps[c];
        float M2 = fmaxf(m, mo);
        if (M2 == -INFINITY) { m = M2; s = 0.f; }
        else { s = s * __expf(m - M2) + so * __expf(mo - M2); m = M2; }
    }
    for (int o = 1; o < 32; o <<= 1) {
        float mo = __shfl_xor_sync(0xffffffffu, m, o);
        float so = __shfl_xor_sync(0xffffffffu, s, o);
        float M2 = fmaxf(m, mo);
        if (M2 == -INFINITY) { m = M2; s = 0.f; }
        else { s = s * __expf(m - M2) + so * __expf(mo - M2); m = M2; }
    }
    if (lane == 0) g_lse[mat * B_ROWS + row] = m + logf(s);
}

// warp per target; bf16 operands (L2-warm), fp32 accumulate
__global__ void loss_kernel(const float* __restrict__ discard,
                            const void* __restrict__ tgt,
                            const void* __restrict__ msk)
{
    int gwarp = (blockIdx.x * blockDim.x + threadIdx.x) >> 5;
    int lane  = threadIdx.x & 31;
    if (gwarp >= B_ROWS * 128) return;
    int b = gwarp >> 7;

    long long v;
    if (g_flags[0]) v = ((const long long*)tgt)[gwarp];
    else            v = (long long)((const int*)tgt)[gwarp];

    float mk;
    if (g_flags[1]) mk = (((const int*)msk)[gwarp] != 0) ? 1.f : 0.f;
    else            mk = (((const unsigned char*)msk)[gwarp] != 0) ? 1.f : 0.f;

    const __nv_bfloat16 *a, *w;
    int Kd; float lse, extra;
    float hlse = g_lse[b];
    if (v < 10000) {
        a = bf_feat + (size_t)b * 1024; w = bf_headW + (size_t)v * 1024;
        Kd = 1024; lse = hlse; extra = 0.f;
    } else if (v < 20000) {
        a = bf_h0 + (size_t)b * 512; w = bf_out0 + (size_t)(v - 10000) * 512;
        Kd = 512; lse = g_lse[1 * B_ROWS + b]; extra = g_tail[b * 4 + 0] - hlse;
    } else if (v < 40000) {
        a = bf_h1 + (size_t)b * 256; w = bf_out1 + (size_t)(v - 20000) * 256;
        Kd = 256; lse = g_lse[2 * B_ROWS + b]; extra = g_tail[b * 4 + 1] - hlse;
    } else if (v < 80000) {
        a = bf_h2 + (size_t)b * 128; w = bf_out2 + (size_t)(v - 40000) * 128;
        Kd = 128; lse = g_lse[3 * B_ROWS + b]; extra = g_tail[b * 4 + 2] - hlse;
    } else {
        a = bf_h3 + (size_t)b * 64; w = bf_out3 + (size_t)(v - 80000) * 64;
        Kd = 64; lse = g_lse[4 * B_ROWS + b]; extra = g_tail[b * 4 + 3] - hlse;
    }

    float dot = 0.f;
    for (int k = lane * 8; k < Kd; k += 256) {
        const uint4 av = *(const uint4*)(a + k);
        const uint4 wv = *(const uint4*)(w + k);
        const uint32_t aw[4] = {av.x, av.y, av.z, av.w};
        const uint32_t ww[4] = {wv.x, wv.y, wv.z, wv.w};
#pragma unroll
        for (int j = 0; j < 4; j++) {
            const float2 af2 = __bfloat1622float2(*(const __nv_bfloat162*)&aw[j]);
            const float2 wf2 = __bfloat1622float2(*(const __nv_bfloat162*)&ww[j]);
            dot += af2.x * wf2.x + af2.y * wf2.y;
        }
    }
#pragma unroll
    for (int o = 16; o >= 1; o >>= 1) dot += __shfl_xor_sync(0xffffffffu, dot, o);

    if (lane == 0) {
        float lp = dot - lse + extra;
        float wt = (1.f - discard[v]) * mk;
        atomicAdd(&g_num[b], -lp * wt);
        atomicAdd(&g_den[b], wt);
    }
}

__global__ void final_kernel(float* out) {
    __shared__ float red[256];
    float s = 0.f;
    for (int i = threadIdx.x; i < B_ROWS; i += 256) s += g_num[i] / g_den[i];
    red[threadIdx.x] = s;
    __syncthreads();
    for (int o = 128; o >= 1; o >>= 1) {
        if (threadIdx.x < o) red[threadIdx.x] += red[threadIdx.x + o];
        __syncthreads();
    }
    if (threadIdx.x == 0)
        out[0] = (float)((double)red[0] / (1024.0 + 1e-5));
}

// ============================================================================
extern "C" void kernel_launch(void* const* d_in, const int* in_sizes, int n_in,
                              void* d_out, int out_size)
{
    const float* feat    = (const float*)d_in[0];
    const float* headW   = (const float*)d_in[1];
    const float* proj0   = (const float*)d_in[2];
    const float* out0    = (const float*)d_in[3];
    const float* proj1   = (const float*)d_in[4];
    const float* out1    = (const float*)d_in[5];
    const float* proj2   = (const float*)d_in[6];
    const float* out2    = (const float*)d_in[7];
    const float* proj3   = (const float*)d_in[8];
    const float* out3    = (const float*)d_in[9];
    const float* discard = (const float*)d_in[10];
    const void*  tgt     = d_in[11];
    const void*  msk     = d_in[12];
    float* out = (float*)d_out;

    cudaFuncSetAttribute(proj_kernel, cudaFuncAttributeMaxDynamicSharedMemorySize, SMEM_SZ);
    cudaFuncSetAttribute(lse_kernel,  cudaFuncAttributeMaxDynamicSharedMemorySize, SMEM_SZ);

    init_kernel<<<1, 1024>>>(tgt, msk);
    cvt_all<<<4096, 256>>>(feat, headW, out0, out1, out2, out3,
                           proj0, proj1, proj2, proj3);
    proj_kernel<<<dim3(8, 5),   512, SMEM_SZ>>>();
    lse_kernel<<<dim3(8, 395),  512, SMEM_SZ>>>();
    combine_kernel<<<dim3(1024, 5), 32>>>();
    loss_kernel<<<16384, 256>>>(discard, tgt, msk);
    final_kernel<<<1, 256>>>(out);
}